// round 9
// baseline (speedup 1.0000x reference)
#include <cuda_runtime.h>

#define TB      64      // batch rows per CTA
#define RPAD    66      // row stride (floats), even => aligned float2 row-pairs
#define NTHREADS 512
#define OMEGA_F 30.0f

// ---------- f32x2 packed math (Blackwell FFMA2) ----------
static __device__ __forceinline__ unsigned long long pack2(float a, float b) {
    unsigned long long r;
    asm("mov.b64 %0, {%1, %2};" : "=l"(r) : "f"(a), "f"(b));
    return r;
}
static __device__ __forceinline__ void unpack2(unsigned long long v, float &a, float &b) {
    asm("mov.b64 {%0, %1}, %2;" : "=f"(a), "=f"(b) : "l"(v));
}
static __device__ __forceinline__ unsigned long long fma2(unsigned long long a,
                                                          unsigned long long b,
                                                          unsigned long long c) {
    unsigned long long d;
    asm("fma.rn.f32x2 %0, %1, %2, %3;" : "=l"(d) : "l"(a), "l"(b), "l"(c));
    return d;
}

// ---------------------------------------------------------------------------
// Reformatted weight store: per layer, [K/2][N] ulonglong2,
//   elem(k2,n) = { pack2(W[n][2k2],W[n][2k2]), pack2(W[n][2k2+1],W[n][2k2+1]) }
// ---------------------------------------------------------------------------
#define OFF_ENC1 0
#define OFF_ENC2 4096
#define OFF_RES1 20480
#define OFF_RES2 36864
#define OFF_RES3 45056
#define OFF_POL1 61440
#define OFF_POL2 61696
#define OFF_EXP1 69888
#define OFF_EXP2 299264
#define WT_TOTAL 528640

__device__ ulonglong2 g_wt[WT_TOTAL];

__global__ void reformat_w(const float* __restrict__ src, int dst_off,
                           int N, int K, int NB)
{
    int idx = blockIdx.x * blockDim.x + threadIdx.x;
    int K2 = K / 2;
    int total = NB * K2 * N;
    if (idx >= total) return;
    int n  = idx % N;
    int t  = idx / N;
    int k2 = t % K2;
    int nb = t / K2;
    const float* s = src + ((long long)(nb * N + n)) * K + 2 * k2;
    float w0 = s[0], w1 = s[1];
    ulonglong2 v;
    v.x = pack2(w0, w0);
    v.y = pack2(w1, w1);
    g_wt[dst_off + idx] = v;
}

// Shared memory layout (floats)
#define SM_BUFE 0
#define SM_BUFT (256 * RPAD)
#define SM_BUFU (2 * 256 * RPAD)
#define SM_WBUF (3 * 256 * RPAD)            // 16 KB weight stage (ulonglong2)
#define SM_XS   (SM_WBUF + 4096)
#define SM_PROB (SM_XS + 4 * RPAD)
#define SM_YACC (SM_PROB + 7 * TB)
#define SM_SCR  (SM_YACC + TB)
#define SM_TOTAL (SM_SCR + 8 * TB)

// ---------------------------------------------------------------------------
// Fused GEMM layer, smem-staged pre-duplicated weights.
//   in  : smem activations, [K][RPAD] feature-major
//   Wt  : g_wt region, [K/2][N] ulonglong2
//   out : smem activations, [N][RPAD]
//   ACT : 0 = sin(OMEGA*z), 1 = relu(z), 2 = relu(z + res)
// 512 threads, 16 warps; warp owns 4 rows (2 row-pairs); cols n = lane + 32j.
// Chunk = 16 KB of dup'd weights (CK = 1024/N k-pairs), register-prefetched.
// Per k-pair per thread: 4 LDS.64 (a) + NCOL LDS.128 (w) + 4*NCOL FFMA2.
// ---------------------------------------------------------------------------
template <int K, int NCOL, int ACT>
static __device__ __forceinline__ void gemm_s(
    const float* __restrict__ in, const ulonglong2* __restrict__ Wt,
    const float* __restrict__ bias, float* __restrict__ out,
    ulonglong2* __restrict__ wbuf, const float* __restrict__ res)
{
    constexpr int N   = NCOL * 32;
    constexpr int K2  = K / 2;
    constexpr int CK  = 1024 / N;            // k-pairs per 16KB chunk (4 or 8)
    static_assert(K2 % CK == 0, "K2 % CK");

    const int tid  = threadIdx.x;
    const int lane = tid & 31;
    const int warp = tid >> 5;
    const int r0   = warp * 4;

    unsigned long long acc[2][NCOL];
#pragma unroll
    for (int i = 0; i < 2; i++)
#pragma unroll
        for (int j = 0; j < NCOL; j++) acc[i][j] = 0ull;

    // prefetch chunk 0 (2 ulonglong2 per thread)
    ulonglong2 wr[2];
#pragma unroll
    for (int l = 0; l < 2; l++)
        wr[l] = __ldg(Wt + tid + NTHREADS * l);

    for (int c = 0; c < K2 / CK; c++) {
        // commit prefetched chunk
#pragma unroll
        for (int l = 0; l < 2; l++)
            wbuf[tid + NTHREADS * l] = wr[l];
        __syncthreads();

        // prefetch next chunk
        if ((c + 1) * CK < K2) {
            const ulonglong2* src = Wt + (c + 1) * (CK * N);
#pragma unroll
            for (int l = 0; l < 2; l++)
                wr[l] = __ldg(src + tid + NTHREADS * l);
        }

#pragma unroll
        for (int kc = 0; kc < CK; kc++) {
            const int k = 2 * (c * CK + kc);
            const float* a0p = in + k * RPAD + r0;
            const float* a1p = a0p + RPAD;
            unsigned long long a0[2], a1[2];
#pragma unroll
            for (int i = 0; i < 2; i++) {        // broadcast LDS.64 row-pairs
                a0[i] = *(const unsigned long long*)(a0p + 2 * i);
                a1[i] = *(const unsigned long long*)(a1p + 2 * i);
            }
            const ulonglong2* wrow = wbuf + kc * N + lane;
#pragma unroll
            for (int j = 0; j < NCOL; j++) {
                ulonglong2 w = wrow[32 * j];     // LDS.128, conflict-free
#pragma unroll
                for (int i = 0; i < 2; i++) acc[i][j] = fma2(a0[i], w.x, acc[i][j]);
#pragma unroll
                for (int i = 0; i < 2; i++) acc[i][j] = fma2(a1[i], w.y, acc[i][j]);
            }
        }
        __syncthreads();
    }

    // epilogue: bias + activation, store transposed [n][row] as float2
#pragma unroll
    for (int j = 0; j < NCOL; j++) {
        int n = lane + 32 * j;
        float b = __ldg(bias + n);
#pragma unroll
        for (int i = 0; i < 2; i++) {
            float z0, z1;
            unpack2(acc[i][j], z0, z1);
            z0 += b; z1 += b;
            if (ACT == 0) {
                z0 = __sinf(OMEGA_F * z0);
                z1 = __sinf(OMEGA_F * z1);
            } else if (ACT == 1) {
                z0 = fmaxf(z0, 0.0f);
                z1 = fmaxf(z1, 0.0f);
            } else {
                float2 rv = *(const float2*)(res + n * RPAD + r0 + 2 * i);
                z0 = fmaxf(z0 + rv.x, 0.0f);
                z1 = fmaxf(z1 + rv.y, 0.0f);
            }
            *(float2*)(out + n * RPAD + r0 + 2 * i) = make_float2(z0, z1);
        }
    }
    __syncthreads();
}

// Small-K variant: whole weight staged at once (K2*N <= 1024). For pol_s1 (K=4).
template <int K, int NCOL, int ACT>
static __device__ __forceinline__ void gemm_small(
    const float* __restrict__ in, const ulonglong2* __restrict__ Wt,
    const float* __restrict__ bias, float* __restrict__ out,
    ulonglong2* __restrict__ wbuf)
{
    constexpr int N  = NCOL * 32;
    constexpr int K2 = K / 2;
    const int tid  = threadIdx.x;
    const int lane = tid & 31;
    const int warp = tid >> 5;
    const int r0   = warp * 4;

    for (int idx = tid; idx < K2 * N; idx += NTHREADS)
        wbuf[idx] = __ldg(Wt + idx);
    __syncthreads();

    unsigned long long acc[2][NCOL];
#pragma unroll
    for (int i = 0; i < 2; i++)
#pragma unroll
        for (int j = 0; j < NCOL; j++) acc[i][j] = 0ull;

#pragma unroll
    for (int k2 = 0; k2 < K2; k2++) {
        const int k = 2 * k2;
        const float* a0p = in + k * RPAD + r0;
        const float* a1p = a0p + RPAD;
        unsigned long long a0[2], a1[2];
#pragma unroll
        for (int i = 0; i < 2; i++) {
            a0[i] = *(const unsigned long long*)(a0p + 2 * i);
            a1[i] = *(const unsigned long long*)(a1p + 2 * i);
        }
        const ulonglong2* wrow = wbuf + k2 * N + lane;
#pragma unroll
        for (int j = 0; j < NCOL; j++) {
            ulonglong2 w = wrow[32 * j];
#pragma unroll
            for (int i = 0; i < 2; i++) acc[i][j] = fma2(a0[i], w.x, acc[i][j]);
#pragma unroll
            for (int i = 0; i < 2; i++) acc[i][j] = fma2(a1[i], w.y, acc[i][j]);
        }
    }

#pragma unroll
    for (int j = 0; j < NCOL; j++) {
        int n = lane + 32 * j;
        float b = __ldg(bias + n);
#pragma unroll
        for (int i = 0; i < 2; i++) {
            float z0, z1;
            unpack2(acc[i][j], z0, z1);
            z0 += b; z1 += b;
            if (ACT == 0) {
                z0 = __sinf(OMEGA_F * z0);
                z1 = __sinf(OMEGA_F * z1);
            } else {
                z0 = fmaxf(z0, 0.0f);
                z1 = fmaxf(z1, 0.0f);
            }
            *(float2*)(out + n * RPAD + r0 + 2 * i) = make_float2(z0, z1);
        }
    }
    __syncthreads();
}

// ---------------------------------------------------------------------------
__global__ void __launch_bounds__(NTHREADS, 1)
moe_inr_kernel(
    const float* __restrict__ x,
    const float* __restrict__ enc_s1_b, const float* __restrict__ enc_s2_b,
    const float* __restrict__ res_fc1_b, const float* __restrict__ res_fc2_b,
    const float* __restrict__ res_fc3_b,
    const float* __restrict__ pol_s1_b, const float* __restrict__ pol_s2_b,
    const float* __restrict__ gate_w, const float* __restrict__ gate_b,
    const float* __restrict__ exp_s1_b, const float* __restrict__ exp_s2_b,
    const float* __restrict__ exp_fin_w, const float* __restrict__ exp_fin_b,
    float* __restrict__ out)
{
    extern __shared__ float smem[];
    float* bufE  = smem + SM_BUFE;
    float* bufT  = smem + SM_BUFT;
    float* bufU  = smem + SM_BUFU;
    ulonglong2* wbuf = (ulonglong2*)(smem + SM_WBUF);
    float* xs    = smem + SM_XS;
    float* probs = smem + SM_PROB;
    float* yacc  = smem + SM_YACC;
    float* scr   = smem + SM_SCR;

    const int tid = threadIdx.x;
    const long long rowbase = (long long)blockIdx.x * TB;

    // ---- load x tile: [4][RPAD] feature-major ----
    if (tid < TB * 4) {
        int r = tid >> 2, d = tid & 3;
        xs[d * RPAD + r] = x[(rowbase + r) * 4 + d];
    }
    __syncthreads();

    // ---- positional encoding -> bufT rows [0,64): col = d*16+f; f<8 sin else cos ----
    for (int idx = tid; idx < 64 * TB; idx += NTHREADS) {
        int r = idx & (TB - 1), c = idx / TB;
        int d = c >> 4, f = c & 15;
        float freq = exp2f((float)(f & 7)) * 3.14159265358979323846f;
        float ang  = xs[d * RPAD + r] * freq;
        bufT[c * RPAD + r] = (f < 8) ? sinf(ang) : cosf(ang);
    }
    __syncthreads();

    // ---- encoder ----
    gemm_s< 64, 4, 0>(bufT, g_wt + OFF_ENC1, enc_s1_b,  bufU, wbuf, nullptr);
    gemm_s<128, 8, 0>(bufU, g_wt + OFF_ENC2, enc_s2_b,  bufE, wbuf, nullptr);
    gemm_s<256, 4, 1>(bufE, g_wt + OFF_RES1, res_fc1_b, bufT, wbuf, nullptr);
    gemm_s<128, 4, 1>(bufT, g_wt + OFF_RES2, res_fc2_b, bufU, wbuf, nullptr);
    gemm_s<128, 8, 2>(bufU, g_wt + OFF_RES3, res_fc3_b, bufE, wbuf, bufE);

    // ---- policy ----
    gemm_small<4, 4, 0>(xs, g_wt + OFF_POL1, pol_s1_b, bufT, wbuf);
    gemm_s<128, 4, 0>(bufT, g_wt + OFF_POL2, pol_s2_b, bufU, wbuf, nullptr);

    // ---- gate: logits over concat(enc_feat[256], pf[128]) ----
    float* gbuf = bufT;   // dead; 16896 floats available
    for (int idx = tid; idx < 7 * 384; idx += NTHREADS) gbuf[idx] = gate_w[idx];
    __syncthreads();
    if (tid < 7 * TB) {
        int r = tid & (TB - 1), c = tid / TB;
        const float* gw = gbuf + c * 384;
        float s = __ldg(gate_b + c);
        for (int k = 0; k < 256; k++) s += bufE[k * RPAD + r] * gw[k];
        for (int k = 0; k < 128; k++) s += bufU[k * RPAD + r] * gw[256 + k];
        probs[c * TB + r] = s;
    }
    __syncthreads();
    if (tid < TB) {
        int r = tid;
        float m = -1e30f;
        for (int c = 0; c < 7; c++) m = fmaxf(m, probs[c * TB + r]);
        float s = 0.0f, e[7];
        for (int c = 0; c < 7; c++) { e[c] = __expf(probs[c * TB + r] - m); s += e[c]; }
        float inv = 1.0f / s;
        for (int c = 0; c < 7; c++) probs[c * TB + r] = e[c] * inv;
        yacc[r] = 0.0f;
    }
    __syncthreads();

    // ---- experts ----
    for (int e = 0; e < 7; e++) {
        gemm_s<256, 8, 0>(bufE, g_wt + OFF_EXP1 + e * 32768,
                          exp_s1_b + e * 256, bufT, wbuf, nullptr);
        gemm_s<256, 8, 0>(bufT, g_wt + OFF_EXP2 + e * 32768,
                          exp_s2_b + e * 256, bufU, wbuf, nullptr);
        // final linear [256]->1, 8-way split reduction per row
        {
            int part = tid >> 6, r = tid & 63;
            const float* Wf = exp_fin_w + e * 256;
            float s = 0.0f;
            int k0 = part * 32;
            for (int k = k0; k < k0 + 32; k++) s += bufU[k * RPAD + r] * __ldg(Wf + k);
            scr[part * TB + r] = s;
        }
        __syncthreads();
        if (tid < TB) {
            int r = tid;
            float pred = __ldg(exp_fin_b + e);
#pragma unroll
            for (int p = 0; p < 8; p++) pred += scr[p * TB + r];
            yacc[r] += probs[e * TB + r] * pred;
        }
        __syncthreads();
    }

    if (tid < TB) out[rowbase + tid] = yacc[tid];
}

// ---------------------------------------------------------------------------
static inline void launch_reformat(const float* src, int dst_off, int N, int K, int NB)
{
    int total = NB * (K / 2) * N;
    reformat_w<<<(total + 255) / 256, 256>>>(src, dst_off, N, K, NB);
}

extern "C" void kernel_launch(void* const* d_in, const int* in_sizes, int n_in,
                              void* d_out, int out_size)
{
    const float* x         = (const float*)d_in[0];
    const float* enc_s1_w  = (const float*)d_in[1];
    const float* enc_s1_b  = (const float*)d_in[2];
    const float* enc_s2_w  = (const float*)d_in[3];
    const float* enc_s2_b  = (const float*)d_in[4];
    const float* res_fc1_w = (const float*)d_in[5];
    const float* res_fc1_b = (const float*)d_in[6];
    const float* res_fc2_w = (const float*)d_in[7];
    const float* res_fc2_b = (const float*)d_in[8];
    const float* res_fc3_w = (const float*)d_in[9];
    const float* res_fc3_b = (const float*)d_in[10];
    const float* pol_s1_w  = (const float*)d_in[11];
    const float* pol_s1_b  = (const float*)d_in[12];
    const float* pol_s2_w  = (const float*)d_in[13];
    const float* pol_s2_b  = (const float*)d_in[14];
    const float* gate_w    = (const float*)d_in[15];
    const float* gate_b    = (const float*)d_in[16];
    const float* exp_s1_w  = (const float*)d_in[17];
    const float* exp_s1_b  = (const float*)d_in[18];
    const float* exp_s2_w  = (const float*)d_in[19];
    const float* exp_s2_b  = (const float*)d_in[20];
    const float* exp_fin_w = (const float*)d_in[21];
    const float* exp_fin_b = (const float*)d_in[22];

    launch_reformat(enc_s1_w,  OFF_ENC1, 128,  64, 1);
    launch_reformat(enc_s2_w,  OFF_ENC2, 256, 128, 1);
    launch_reformat(res_fc1_w, OFF_RES1, 128, 256, 1);
    launch_reformat(res_fc2_w, OFF_RES2, 128, 128, 1);
    launch_reformat(res_fc3_w, OFF_RES3, 256, 128, 1);
    launch_reformat(pol_s1_w,  OFF_POL1, 128,   4, 1);
    launch_reformat(pol_s2_w,  OFF_POL2, 128, 128, 1);
    launch_reformat(exp_s1_w,  OFF_EXP1, 256, 256, 7);
    launch_reformat(exp_s2_w,  OFF_EXP2, 256, 256, 7);

    int B = in_sizes[0] / 4;
    int grid = B / TB;
    size_t shmem = (size_t)SM_TOTAL * sizeof(float);

    cudaFuncSetAttribute(moe_inr_kernel,
                         cudaFuncAttributeMaxDynamicSharedMemorySize, (int)shmem);

    moe_inr_kernel<<<grid, NTHREADS, shmem>>>(
        x, enc_s1_b, enc_s2_b,
        res_fc1_b, res_fc2_b, res_fc3_b,
        pol_s1_b, pol_s2_b, gate_w, gate_b,
        exp_s1_b, exp_s2_b, exp_fin_w, exp_fin_b,
        (float*)d_out);
}

// round 11
// speedup vs baseline: 5.2042x; 5.2042x over previous
#include <cuda_runtime.h>
#include <cuda_bf16.h>
#include <cstdint>

#define NTHREADS 256
#define TB       64
#define OMEGA_F  30.0f

// ---------------- helpers ----------------
static __device__ __forceinline__ uint32_t smem_u32(const void* p) {
    uint32_t a;
    asm("{ .reg .u64 t; cvta.to.shared.u64 t, %1; cvt.u32.u64 %0, t; }" : "=r"(a) : "l"(p));
    return a;
}
static __device__ __forceinline__ void ldsm_x4(uint32_t* r, uint32_t a) {
    asm volatile("ldmatrix.sync.aligned.m8n8.x4.shared.b16 {%0,%1,%2,%3}, [%4];"
        : "=r"(r[0]), "=r"(r[1]), "=r"(r[2]), "=r"(r[3]) : "r"(a));
}
static __device__ __forceinline__ void ldsm_x2(uint32_t* r, uint32_t a) {
    asm volatile("ldmatrix.sync.aligned.m8n8.x2.shared.b16 {%0,%1}, [%2];"
        : "=r"(r[0]), "=r"(r[1]) : "r"(a));
}
static __device__ __forceinline__ void mma16816(float* d, const uint32_t* a, const uint32_t* b) {
    asm volatile("mma.sync.aligned.m16n8k16.row.col.f32.bf16.bf16.f32 "
        "{%0,%1,%2,%3}, {%4,%5,%6,%7}, {%8,%9}, {%0,%1,%2,%3};"
        : "+f"(d[0]), "+f"(d[1]), "+f"(d[2]), "+f"(d[3])
        : "r"(a[0]), "r"(a[1]), "r"(a[2]), "r"(a[3]), "r"(b[0]), "r"(b[1]));
}
static __device__ __forceinline__ void split_pair(float a0, float a1, uint32_t& hi, uint32_t& lo) {
    __nv_bfloat16 h0 = __float2bfloat16(a0), h1 = __float2bfloat16(a1);
    __nv_bfloat16 q0 = __float2bfloat16(a0 - __bfloat162float(h0));
    __nv_bfloat16 q1 = __float2bfloat16(a1 - __bfloat162float(h1));
    hi = ((uint32_t)__bfloat16_as_ushort(h1) << 16) | __bfloat16_as_ushort(h0);
    lo = ((uint32_t)__bfloat16_as_ushort(q1) << 16) | __bfloat16_as_ushort(q0);
}
static __device__ __forceinline__ float join_w(uint32_t h, uint32_t l, int hi16) {
    unsigned short hs = hi16 ? (unsigned short)(h >> 16) : (unsigned short)(h & 0xFFFF);
    unsigned short ls = hi16 ? (unsigned short)(l >> 16) : (unsigned short)(l & 0xFFFF);
    return __bfloat162float(__ushort_as_bfloat16(hs)) + __bfloat162float(__ushort_as_bfloat16(ls));
}
// activation byte offset: [m][k] bf16, stride SK, 16B-chunk XOR swizzle
static __device__ __forceinline__ uint32_t abyteA(int m, int k, int SK) {
    return (uint32_t)m * (uint32_t)(SK * 2)
         + (uint32_t)((((k >> 3) ^ (m & 7)) << 4) + (k & 7) * 2);
}

// ---------------- weight blob (pre-split hi/lo, pre-swizzled) ----------------
// layer region: fills = (K/64)*2, fill f: chunk kc=f>>1, half=f&1 (0=hi,1=lo)
// fill = [N][64] bf16, row=128B, chunk swizzle ((kk>>3) ^ (n&7))
#define BO_ENC1 0
#define BO_ENC2 32768
#define BO_RES1 163840
#define BO_RES2 294912
#define BO_RES3 360448
#define BO_POL2 491520
#define BO_EXP1 557056
#define BO_EXP2 2392064
#define BLOB_BYTES 4227072
__device__ __align__(16) uint8_t g_blob[BLOB_BYTES];

__global__ void reformat_w(const float* __restrict__ src, int blob_off, int N, int K, int NB)
{
    int idx = blockIdx.x * blockDim.x + threadIdx.x;
    long long total = (long long)NB * N * K;
    if (idx >= total) return;
    int k  = idx % K;
    int n  = (idx / K) % N;
    int nb = idx / (K * N);
    float w = src[idx];
    __nv_bfloat16 h = __float2bfloat16(w);
    __nv_bfloat16 l = __float2bfloat16(w - __bfloat162float(h));
    int per_nb = (K / 64) * 2 * (N * 128);
    int kc = k >> 6, kk = k & 63;
    int base = blob_off + nb * per_nb + kc * 2 * (N * 128);
    uint32_t byte = (uint32_t)n * 128u + (uint32_t)((((kk >> 3) ^ (n & 7)) << 4) + (kk & 7) * 2);
    *(__nv_bfloat16*)(g_blob + base + byte)           = h;
    *(__nv_bfloat16*)(g_blob + base + N * 128 + byte) = l;
}

// ---------------- SMEM layout (bytes) ----------------
#define SMB_W0    0
#define SMB_W1    32768
#define SMB_ABH   65536     // A_big hi [64][256] bf16
#define SMB_ABL   98304
#define SMB_AEH   131072    // A_exp hi [64][<=256] bf16
#define SMB_AEL   163840
#define SMB_XS    196608    // [4][64] f32
#define SMB_PROBS 197632    // [7][64] f32
#define SMB_YACC  199424    // [64] f32
#define SMB_SCR   199680    // [4][64] f32
#define SMB_TOTAL 200704

// ---------------- fused MMA layer ----------------
// MODE 0: sin -> dest   1: relu -> dest   2: relu(D+b+dest) -> dest (residual)
// MODE 3: sin, dot with extra (fin_w) -> scr partials
template <int K, int N, int MODE, int SKA, int SKD>
static __device__ void layer(char* smem, const uint8_t* blob,
                             uint32_t aHi, uint32_t aLo,
                             char* dHi, char* dLo,
                             const float* bias, const float* extra)
{
    constexpr int FILLS = (K / 64) * 2;
    constexpr int LD = N / 32;      // uint4 per thread per fill
    constexpr int NT = N / 32;      // 8x-n tiles per warp
    const int tid = threadIdx.x, lane = tid & 31, warp = tid >> 5;
    const int warp_m = warp & 1, warp_n = warp >> 1;
    const int nh = warp_n * (N / 4);

    float d[2][NT][4];
#pragma unroll
    for (int mt = 0; mt < 2; mt++)
#pragma unroll
        for (int nt = 0; nt < NT; nt++)
#pragma unroll
            for (int i = 0; i < 4; i++) d[mt][nt][i] = 0.0f;

    const int g = lane >> 3;
    const int mlocal = (lane & 7) + (g & 1) * 8;
    const int chA = g >> 1;
    const int bi = lane & 7, bsel = (lane >> 3) & 1;

    uint4 pf[LD];
    const uint4* gsrc = (const uint4*)blob;
#pragma unroll
    for (int l = 0; l < LD; l++) pf[l] = __ldg(gsrc + tid + 256 * l);

    for (int f = 0; f < FILLS; f++) {
        uint4* ws = (uint4*)(smem + ((f & 1) ? SMB_W1 : SMB_W0));
#pragma unroll
        for (int l = 0; l < LD; l++) ws[tid + 256 * l] = pf[l];
        __syncthreads();
        if (f + 1 < FILLS) {
            const uint4* s2 = gsrc + (size_t)(f + 1) * (N * 8);
#pragma unroll
            for (int l = 0; l < LD; l++) pf[l] = __ldg(s2 + tid + 256 * l);
        }
        const uint32_t wb = smem_u32(smem + ((f & 1) ? SMB_W1 : SMB_W0));
        const int kc = f >> 1, whalf = f & 1;
#pragma unroll
        for (int kk4 = 0; kk4 < 4; kk4++) {
            const int k0 = kc * 64 + kk4 * 16;
            uint32_t ah[2][4], al[2][4];
#pragma unroll
            for (int mt = 0; mt < 2; mt++) {
                const int m = warp_m * 32 + mt * 16 + mlocal;
                const uint32_t off = (uint32_t)m * (uint32_t)(SKA * 2)
                    + (uint32_t)(((((k0 >> 3) + chA) ^ (m & 7)) << 4));
                ldsm_x4(ah[mt], aHi + off);
                if (!whalf) ldsm_x4(al[mt], aLo + off);
            }
#pragma unroll
            for (int nt = 0; nt < NT; nt++) {
                const int n = nh + nt * 8 + bi;
                const uint32_t boff = (uint32_t)n * 128u
                    + (uint32_t)((((kk4 * 2 + bsel) ^ (n & 7)) << 4));
                uint32_t b[2];
                ldsm_x2(b, wb + boff);
                mma16816(d[0][nt], ah[0], b);
                mma16816(d[1][nt], ah[1], b);
                if (!whalf) {
                    mma16816(d[0][nt], al[0], b);
                    mma16816(d[1][nt], al[1], b);
                }
            }
        }
    }
    __syncthreads();   // all A reads + W-buf use complete before epilogue writes

    float pred[2][2] = {{0.0f, 0.0f}, {0.0f, 0.0f}};
#pragma unroll
    for (int mt = 0; mt < 2; mt++) {
        const int m1 = warp_m * 32 + mt * 16 + (lane >> 2);
        const int m2 = m1 + 8;
#pragma unroll
        for (int nt = 0; nt < NT; nt++) {
            const int nc = nh + nt * 8 + 2 * (lane & 3);
            const float b0 = __ldg(bias + nc), b1 = __ldg(bias + nc + 1);
            float v00 = d[mt][nt][0] + b0, v01 = d[mt][nt][1] + b1;
            float v10 = d[mt][nt][2] + b0, v11 = d[mt][nt][3] + b1;
            if (MODE == 3) {
                const float w0 = __ldg(extra + nc), w1 = __ldg(extra + nc + 1);
                pred[mt][0] += w0 * __sinf(OMEGA_F * v00) + w1 * __sinf(OMEGA_F * v01);
                pred[mt][1] += w0 * __sinf(OMEGA_F * v10) + w1 * __sinf(OMEGA_F * v11);
            } else {
                const uint32_t o1 = abyteA(m1, nc, SKD);
                const uint32_t o2 = abyteA(m2, nc, SKD);
                if (MODE == 2) {
                    uint32_t hh = *(uint32_t*)(dHi + o1), ll = *(uint32_t*)(dLo + o1);
                    v00 += join_w(hh, ll, 0); v01 += join_w(hh, ll, 1);
                    hh = *(uint32_t*)(dHi + o2); ll = *(uint32_t*)(dLo + o2);
                    v10 += join_w(hh, ll, 0); v11 += join_w(hh, ll, 1);
                }
                float s00, s01, s10, s11;
                if (MODE == 0) {
                    s00 = __sinf(OMEGA_F * v00); s01 = __sinf(OMEGA_F * v01);
                    s10 = __sinf(OMEGA_F * v10); s11 = __sinf(OMEGA_F * v11);
                } else {
                    s00 = fmaxf(v00, 0.0f); s01 = fmaxf(v01, 0.0f);
                    s10 = fmaxf(v10, 0.0f); s11 = fmaxf(v11, 0.0f);
                }
                uint32_t hi, lo;
                split_pair(s00, s01, hi, lo);
                *(uint32_t*)(dHi + o1) = hi; *(uint32_t*)(dLo + o1) = lo;
                split_pair(s10, s11, hi, lo);
                *(uint32_t*)(dHi + o2) = hi; *(uint32_t*)(dLo + o2) = lo;
            }
        }
    }
    if (MODE == 3) {
        float* scr = (float*)(smem + SMB_SCR);
#pragma unroll
        for (int mt = 0; mt < 2; mt++)
#pragma unroll
            for (int h = 0; h < 2; h++) {
                float p = pred[mt][h];
                p += __shfl_xor_sync(0xFFFFFFFFu, p, 1);
                p += __shfl_xor_sync(0xFFFFFFFFu, p, 2);
                if ((lane & 3) == 0)
                    scr[warp_n * 64 + warp_m * 32 + mt * 16 + (lane >> 2) + h * 8] = p;
            }
    }
}

// ---------------- main kernel ----------------
__global__ void __launch_bounds__(NTHREADS)
moe_inr_kernel(
    const float* __restrict__ x,
    const float* __restrict__ enc_s1_b, const float* __restrict__ enc_s2_b,
    const float* __restrict__ res_fc1_b, const float* __restrict__ res_fc2_b,
    const float* __restrict__ res_fc3_b,
    const float* __restrict__ pol_s1_w, const float* __restrict__ pol_s1_b,
    const float* __restrict__ pol_s2_b,
    const float* __restrict__ gate_w, const float* __restrict__ gate_b,
    const float* __restrict__ exp_s1_b, const float* __restrict__ exp_s2_b,
    const float* __restrict__ exp_fin_w, const float* __restrict__ exp_fin_b,
    float* __restrict__ out)
{
    extern __shared__ char smem[];
    const int tid = threadIdx.x;
    const long long rowbase = (long long)blockIdx.x * TB;
    float* xs    = (float*)(smem + SMB_XS);
    float* probs = (float*)(smem + SMB_PROBS);
    float* yacc  = (float*)(smem + SMB_YACC);
    float* scr   = (float*)(smem + SMB_SCR);
    char* abh = smem + SMB_ABH; char* abl = smem + SMB_ABL;
    char* aeh = smem + SMB_AEH; char* ael = smem + SMB_AEL;
    const uint32_t uABH = smem_u32(abh), uABL = smem_u32(abl);
    const uint32_t uAEH = smem_u32(aeh), uAEL = smem_u32(ael);

    // x tile -> xs[d][m]
    {
        int m = tid >> 2, dd = tid & 3;
        xs[dd * 64 + m] = x[(rowbase + m) * 4 + dd];
    }
    __syncthreads();

    // positional encoding -> A_big (SK=64): col c = d*16+f, f<8 sin else cos
    for (int i = tid; i < 2048; i += NTHREADS) {       // (m, colpair)
        int m = i & 63, jp = i >> 6;
        int c0 = 2 * jp;
        float v[2];
#pragma unroll
        for (int t = 0; t < 2; t++) {
            int c = c0 + t, dd = c >> 4, f = c & 15;
            float ang = xs[dd * 64 + m] * exp2f((float)(f & 7)) * 3.14159265358979323846f;
            v[t] = (f < 8) ? sinf(ang) : cosf(ang);
        }
        uint32_t hi, lo;
        split_pair(v[0], v[1], hi, lo);
        uint32_t off = abyteA(m, c0, 64);
        *(uint32_t*)(abh + off) = hi;
        *(uint32_t*)(abl + off) = lo;
    }
    __syncthreads();

    // encoder
    layer< 64, 128, 0,  64, 128>(smem, g_blob + BO_ENC1, uABH, uABL, aeh, ael, enc_s1_b, nullptr);
    layer<128, 256, 0, 128, 256>(smem, g_blob + BO_ENC2, uAEH, uAEL, abh, abl, enc_s2_b, nullptr);  // h
    layer<256, 128, 1, 256, 128>(smem, g_blob + BO_RES1, uABH, uABL, aeh, ael, res_fc1_b, nullptr);
    layer<128, 128, 1, 128, 128>(smem, g_blob + BO_RES2, uAEH, uAEL, aeh, ael, res_fc2_b, nullptr);
    layer<128, 256, 2, 128, 256>(smem, g_blob + BO_RES3, uAEH, uAEL, abh, abl, res_fc3_b, nullptr); // enc_feat
    __syncthreads();

    // pol_s1 (K=4) scalar -> A_exp (SK=128)
    for (int i = tid; i < 4096; i += NTHREADS) {        // 64 rows x 64 colpairs
        int m = i & 63, np = i >> 6;
        int n0 = 2 * np;
        float x0 = xs[m], x1 = xs[64 + m], x2 = xs[128 + m], x3 = xs[192 + m];
        float4 w0 = __ldg((const float4*)pol_s1_w + n0);
        float4 w1 = __ldg((const float4*)pol_s1_w + n0 + 1);
        float z0 = __ldg(pol_s1_b + n0)     + x0 * w0.x + x1 * w0.y + x2 * w0.z + x3 * w0.w;
        float z1 = __ldg(pol_s1_b + n0 + 1) + x0 * w1.x + x1 * w1.y + x2 * w1.z + x3 * w1.w;
        uint32_t hi, lo;
        split_pair(__sinf(OMEGA_F * z0), __sinf(OMEGA_F * z1), hi, lo);
        uint32_t off = abyteA(m, n0, 128);
        *(uint32_t*)(aeh + off) = hi;
        *(uint32_t*)(ael + off) = lo;
    }
    __syncthreads();

    layer<128, 128, 0, 128, 128>(smem, g_blob + BO_POL2, uAEH, uAEL, aeh, ael, pol_s2_b, nullptr); // pf
    __syncthreads();

    // gate + softmax (1 thread per row)
    if (tid < 64) {
        const int m = tid;
        float lg[7];
#pragma unroll
        for (int c = 0; c < 7; c++) lg[c] = __ldg(gate_b + c);
        for (int k2 = 0; k2 < 128; k2++) {
            uint32_t off = abyteA(m, 2 * k2, 256);
            uint32_t hh = *(uint32_t*)(abh + off), ll = *(uint32_t*)(abl + off);
            float e0 = join_w(hh, ll, 0), e1 = join_w(hh, ll, 1);
#pragma unroll
            for (int c = 0; c < 7; c++)
                lg[c] += e0 * __ldg(gate_w + c * 384 + 2 * k2)
                       + e1 * __ldg(gate_w + c * 384 + 2 * k2 + 1);
        }
        for (int k2 = 0; k2 < 64; k2++) {
            uint32_t off = abyteA(m, 2 * k2, 128);
            uint32_t hh = *(uint32_t*)(aeh + off), ll = *(uint32_t*)(ael + off);
            float p0 = join_w(hh, ll, 0), p1 = join_w(hh, ll, 1);
#pragma unroll
            for (int c = 0; c < 7; c++)
                lg[c] += p0 * __ldg(gate_w + c * 384 + 256 + 2 * k2)
                       + p1 * __ldg(gate_w + c * 384 + 256 + 2 * k2 + 1);
        }
        float mx = -1e30f;
#pragma unroll
        for (int c = 0; c < 7; c++) mx = fmaxf(mx, lg[c]);
        float s = 0.0f;
#pragma unroll
        for (int c = 0; c < 7; c++) { lg[c] = __expf(lg[c] - mx); s += lg[c]; }
        float inv = 1.0f / s;
#pragma unroll
        for (int c = 0; c < 7; c++) probs[c * 64 + m] = lg[c] * inv;
        yacc[m] = 0.0f;
    }
    __syncthreads();

    // experts
    for (int e = 0; e < 7; e++) {
        layer<256, 256, 0, 256, 256>(smem, g_blob + BO_EXP1 + e * 262144,
                                     uABH, uABL, aeh, ael, exp_s1_b + e * 256, nullptr);
        layer<256, 256, 3, 256, 256>(smem, g_blob + BO_EXP2 + e * 262144,
                                     uAEH, uAEL, nullptr, nullptr,
                                     exp_s2_b + e * 256, exp_fin_w + e * 256);
        __syncthreads();
        if (tid < 64) {
            float pred = scr[tid] + scr[64 + tid] + scr[128 + tid] + scr[192 + tid]
                       + __ldg(exp_fin_b + e);
            yacc[tid] += probs[e * 64 + tid] * pred;
        }
        __syncthreads();
    }

    if (tid < 64) out[rowbase + tid] = yacc[tid];
}

// ---------------- host ----------------
static inline void launch_reformat(const float* src, int off, int N, int K, int NB)
{
    long long total = (long long)NB * N * K;
    reformat_w<<<(int)((total + 255) / 256), 256>>>(src, off, N, K, NB);
}

extern "C" void kernel_launch(void* const* d_in, const int* in_sizes, int n_in,
                              void* d_out, int out_size)
{
    const float* x         = (const float*)d_in[0];
    const float* enc_s1_w  = (const float*)d_in[1];
    const float* enc_s1_b  = (const float*)d_in[2];
    const float* enc_s2_w  = (const float*)d_in[3];
    const float* enc_s2_b  = (const float*)d_in[4];
    const float* res_fc1_w = (const float*)d_in[5];
    const float* res_fc1_b = (const float*)d_in[6];
    const float* res_fc2_w = (const float*)d_in[7];
    const float* res_fc2_b = (const float*)d_in[8];
    const float* res_fc3_w = (const float*)d_in[9];
    const float* res_fc3_b = (const float*)d_in[10];
    const float* pol_s1_w  = (const float*)d_in[11];
    const float* pol_s1_b  = (const float*)d_in[12];
    const float* pol_s2_w  = (const float*)d_in[13];
    const float* pol_s2_b  = (const float*)d_in[14];
    const float* gate_w    = (const float*)d_in[15];
    const float* gate_b    = (const float*)d_in[16];
    const float* exp_s1_w  = (const float*)d_in[17];
    const float* exp_s1_b  = (const float*)d_in[18];
    const float* exp_s2_w  = (const float*)d_in[19];
    const float* exp_s2_b  = (const float*)d_in[20];
    const float* exp_fin_w = (const float*)d_in[21];
    const float* exp_fin_b = (const float*)d_in[22];

    launch_reformat(enc_s1_w,  BO_ENC1, 128,  64, 1);
    launch_reformat(enc_s2_w,  BO_ENC2, 256, 128, 1);
    launch_reformat(res_fc1_w, BO_RES1, 128, 256, 1);
    launch_reformat(res_fc2_w, BO_RES2, 128, 128, 1);
    launch_reformat(res_fc3_w, BO_RES3, 256, 128, 1);
    launch_reformat(pol_s2_w,  BO_POL2, 128, 128, 1);
    launch_reformat(exp_s1_w,  BO_EXP1, 256, 256, 7);
    launch_reformat(exp_s2_w,  BO_EXP2, 256, 256, 7);

    int B = in_sizes[0] / 4;
    int grid = B / TB;
    cudaFuncSetAttribute(moe_inr_kernel, cudaFuncAttributeMaxDynamicSharedMemorySize, SMB_TOTAL);
    moe_inr_kernel<<<grid, NTHREADS, SMB_TOTAL>>>(
        x, enc_s1_b, enc_s2_b, res_fc1_b, res_fc2_b, res_fc3_b,
        pol_s1_w, pol_s1_b, pol_s2_b, gate_w, gate_b,
        exp_s1_b, exp_s2_b, exp_fin_w, exp_fin_b, (float*)d_out);
}